// round 11
// baseline (speedup 1.0000x reference)
#include <cuda_runtime.h>
#include <cuda_bf16.h>
#include <cstdint>

#define GH 20        // hidden size
#define GL 5         // layers
#define GT 4096      // timesteps
#define GB 256       // batch
#define GC 16        // chunk (timesteps per superstep)
#define NCHUNK (GT / GC)                 // 256
#define NSUP   (NCHUNK + 2 * (GL - 1))   // 264 (+1 drain superstep in loop)
#define NTHREADS 256                     // 8 warps: 5 rec + 3 inp

using u64 = unsigned long long;
using u32 = unsigned int;

// xp stride: 4 u64 per unit -> (r,z) 16B-aligned pair + n
#define XPS 4

// dynamic smem layout (bytes)
#define XS_OFF    0
#define HCH_OFF   (GT * 8)                                   // 32768
#define XPB_OFF   (HCH_OFF + GL * 2 * GC * GH * 8)           // +25600 = 58368
#define HLAST_OFF (XPB_OFF + (GL - 1) * 2 * GC * GH * XPS * 8) // +81920 = 140288
#define SMEM_SZ   (HLAST_OFF + GL * GH * 8)                  // 141088

#define C1 (-1.4426950408889634f)   // -log2(e)
#define C2 (-2.8853900817779268f)   // -2*log2(e)

struct GruParams {
    const float* x;
    const float* Wih[GL];
    const float* Whh[GL];
    const float* bih[GL];
    const float* bhh[GL];
    const float* Wout;
    const float* bout;
    float* out_h;
    float* out_hn;
    float* out_y;
};

// ---------- packed f32x2 helpers ----------
__device__ __forceinline__ u64 pack2(float lo, float hi) {
    u64 r; asm("mov.b64 %0, {%1,%2};" : "=l"(r) : "f"(lo), "f"(hi)); return r;
}
__device__ __forceinline__ u64 pks(float w) { return pack2(w, w); }
__device__ __forceinline__ void unpack2(u64 v, float& a, float& b) {
    asm("mov.b64 {%0,%1}, %2;" : "=f"(a), "=f"(b) : "l"(v));
}
__device__ __forceinline__ u64 fma2(u64 a, u64 b, u64 c) {
    u64 d; asm("fma.rn.f32x2 %0, %1, %2, %3;" : "=l"(d) : "l"(a), "l"(b), "l"(c)); return d;
}
__device__ __forceinline__ u64 add2(u64 a, u64 b) {
    u64 d; asm("add.rn.f32x2 %0, %1, %2;" : "=l"(d) : "l"(a), "l"(b)); return d;
}

// ---------- warp exchange / predication ----------
__device__ __forceinline__ u64 shfl64(u64 v, int src) {
    u32 lo, hi;
    asm("mov.b64 {%0,%1}, %2;" : "=r"(lo), "=r"(hi) : "l"(v));
    lo = __shfl_sync(0xffffffffu, lo, src);
    hi = __shfl_sync(0xffffffffu, hi, src);
    u64 r; asm("mov.b64 %0, {%1,%2};" : "=l"(r) : "r"(lo), "r"(hi));
    return r;
}
__device__ __forceinline__ u64 selp64(u64 a, u64 b, int c) {
    u64 r;
    asm("{ .reg .pred p; setp.ne.s32 p, %3, 0; selp.b64 %0, %1, %2, p; }"
        : "=l"(r) : "l"(a), "l"(b), "r"(c));
    return r;
}
__device__ __forceinline__ void sts64_pred(u32 addr, u64 v, int pred) {
    asm volatile("{ .reg .pred p; setp.ne.s32 p, %2, 0; @p st.shared.b64 [%0], %1; }"
                 :: "r"(addr), "l"(v), "r"(pred) : "memory");
}
__device__ __forceinline__ void sts128_pred(u32 addr, u64 v0, u64 v1, int pred) {
    asm volatile("{ .reg .pred p; setp.ne.s32 p, %3, 0; @p st.shared.v2.u64 [%0], {%1,%2}; }"
                 :: "r"(addr), "l"(v0), "l"(v1), "r"(pred) : "memory");
}
__device__ __forceinline__ u32 smem_addr(const void* p) {
    return (u32)__cvta_generic_to_shared(p);
}

// ---------- fast activations (args pre-scaled by C1/C2) ----------
__device__ __forceinline__ float fast_exp2(float x) {
    float r; asm("ex2.approx.f32 %0, %1;" : "=f"(r) : "f"(x)); return r;
}
__device__ __forceinline__ float fast_rcp(float x) {
    float r; asm("rcp.approx.f32 %0, %1;" : "=f"(r) : "f"(x)); return r;
}

struct RecW {
    u64 w0[GH], w1[GH], w2[GH];
    u64 bA, bB;                       // rec pass biases (prescaled)
    u64 bias0, bias1, bias2;          // inp biases (prescaled)
    u64 c0r, c0z, c0n, bx0, bx1, bx2; // layer-0 input path (prescaled)
};

__device__ __forceinline__ void gather_hv(const u64* row, u64* hv) {
    const ulonglong2* hp = (const ulonglong2*)row;
#pragma unroll
    for (int q = 0; q < GH / 2; q++) {
        ulonglong2 v = hp[q];
        hv[2 * q] = v.x; hv[2 * q + 1] = v.y;
    }
}

// One GRU step; h-vector gathered by register shuffle from lanes 0..19.
template <bool L0>
__device__ __forceinline__ u64 rec_body(const RecW& W, u64 hu,
                                        const u64* xpt, const u64* xs_t,
                                        int ii, int uz1, int uz2, int un, int selz) {
    // broadcast h vector straight from registers (chain: one shfl latency)
    u32 hlo, hhi;
    asm("mov.b64 {%0,%1}, %2;" : "=r"(hlo), "=r"(hhi) : "l"(hu));
    u64 hv[GH];
#pragma unroll
    for (int k = 0; k < GH; k++) {
        const u32 lo = __shfl_sync(0xffffffffu, hlo, k);
        const u32 hi = __shfl_sync(0xffffffffu, hhi, k);
        asm("mov.b64 %0, {%1,%2};" : "=l"(hv[k]) : "r"(lo), "r"(hi));
    }

    // x inputs (prescaled, off critical path)
    u64 xr, xz, xn;
    if (L0) {
        const u64 xt = *xs_t;
        xr = fma2(W.c0r, xt, W.bx0);
        xz = fma2(W.c0z, xt, W.bx1);
        xn = fma2(W.c0n, xt, W.bx2);
    } else {
        ulonglong2 rz = *(const ulonglong2*)(xpt + (size_t)ii * XPS);
        xr = rz.x; xz = rz.y;
        xn = xpt[(size_t)ii * XPS + 2];
    }

    // pass A (rows 0-31) + pass B (rows 32-59), 4 accumulators each (depth 5+tree)
    u64 aA0 = W.bA, aA1 = 0, aA2 = 0, aA3 = 0;
    u64 aB0 = W.bB, aB1 = 0, aB2 = 0, aB3 = 0;
#pragma unroll
    for (int k = 0; k < GH / 4; k++) {
        aA0 = fma2(W.w0[4 * k],     hv[4 * k],     aA0);
        aA1 = fma2(W.w0[4 * k + 1], hv[4 * k + 1], aA1);
        aA2 = fma2(W.w0[4 * k + 2], hv[4 * k + 2], aA2);
        aA3 = fma2(W.w0[4 * k + 3], hv[4 * k + 3], aA3);
        aB0 = fma2(W.w1[4 * k],     hv[4 * k],     aB0);
        aB1 = fma2(W.w1[4 * k + 1], hv[4 * k + 1], aB1);
        aB2 = fma2(W.w1[4 * k + 2], hv[4 * k + 2], aB2);
        aB3 = fma2(W.w1[4 * k + 3], hv[4 * k + 3], aB3);
    }
    const u64 aA = add2(add2(aA0, aA1), add2(aA2, aA3));
    const u64 aB = add2(add2(aB0, aB1), add2(aB2, aB3));

    // regroup to unit-per-lane
    const u64 azA = shfl64(aA, uz1);
    const u64 azB = shfl64(aB, uz2);
    const u64 an  = shfl64(aB, un);
    const u64 az  = selp64(azA, azB, selz);

    const u64 sr = add2(xr, aA);   // prescaled by C1
    const u64 sz = add2(xz, az);   // prescaled by C1

    float srL, srH, szL, szH, anL, anH, xnL, xnH, hL, hH;
    unpack2(sr, srL, srH);
    unpack2(sz, szL, szH);
    unpack2(an, anL, anH);
    unpack2(xn, xnL, xnH);
    unpack2(hu, hL, hH);

    // separate-rcp sigmoids (shorter chain); hn = fma(n, 1-z, z*h)
    const float eaL  = fast_exp2(srL);
    const float rL   = fast_rcp(1.0f + eaL);
    const float ebL  = fast_exp2(szL);
    const float zL   = fast_rcp(1.0f + ebL);
    const float zhL  = zL * hL;
    const float omzL = 1.0f - zL;
    const float tL   = fast_exp2(fmaf(rL, anL, xnL));     // arg prescaled by C2
    const float nL   = fmaf(2.0f, fast_rcp(1.0f + tL), -1.0f);
    const float hnL  = fmaf(nL, omzL, zhL);

    const float eaH  = fast_exp2(srH);
    const float rH   = fast_rcp(1.0f + eaH);
    const float ebH  = fast_exp2(szH);
    const float zH   = fast_rcp(1.0f + ebH);
    const float zhH  = zH * hH;
    const float omzH = 1.0f - zH;
    const float tH   = fast_exp2(fmaf(rH, anH, xnH));
    const float nH   = fmaf(2.0f, fast_rcp(1.0f + tH), -1.0f);
    const float hnH  = fmaf(nH, omzH, zhH);

    return pack2(hnL, hnH);
}

// One 16-step chunk for a rec warp. Register-carried recurrence; no intra-warp sync.
template <bool L0>
__device__ __forceinline__ u64 rec_chunk(const RecW& W, u64 hu,
                                         u64* hb, const u64* xp, const u64* xs, int tbase,
                                         int ii, int pa,
                                         int uz1, int uz2, int un, int selz) {
    const u32 hb_a = smem_addr(hb) + (u32)ii * 8u;
#pragma unroll 4
    for (int tin = 0; tin < GC; tin++) {
        hu = rec_body<L0>(W, hu, xp + (size_t)tin * GH * XPS, xs + tbase + tin,
                          ii, uz1, uz2, un, selz);
        sts64_pred(hb_a + (u32)(tin * GH) * 8u, hu, pa);   // for inp/out-copy consumers
    }
    return hu;
}

__global__ __launch_bounds__(NTHREADS, 1) void gru_chunked_kernel(GruParams p) {
    extern __shared__ __align__(16) unsigned char sm[];
    u64* xs    = (u64*)(sm + XS_OFF);    // [GT] packed x
    u64* hch   = (u64*)(sm + HCH_OFF);   // [GL][2][GC][GH]
    u64* xpb   = (u64*)(sm + XPB_OFF);   // [GL-1][2][GC][GH][XPS]
    u64* hlast = (u64*)(sm + HLAST_OFF); // [GL*GH]

    const int tid  = threadIdx.x;
    const int wid  = tid >> 5;
    const int lane = tid & 31;
    const int b0   = blockIdx.x * 2;
    const int b1   = b0 + 1;

    const float* x0 = p.x + (size_t)b0 * GT;
    const float* x1 = p.x + (size_t)b1 * GT;
    for (int t = tid; t < GT; t += NTHREADS) xs[t] = pack2(x0[t], x1[t]);
    for (int q = tid; q < GL * 2 * GC * GH; q += NTHREADS) hch[q] = 0ull;

    // ---- roles ----
    const bool isRec = (wid < GL);
    int l, i;
    bool act;
    if (isRec) { l = wid; i = lane; act = (lane < GH); }
    else {
        int idx = (wid - GL) * 32 + lane;          // 0..95
        act = (idx < (GL - 1) * GH);               // 80 tasks
        l = act ? 1 + idx / GH : 1;
        i = act ? idx % GH : 0;
    }
    const int ii = (i < GH) ? i : 0;
    const int pa = act ? 1 : 0;

    // shuffle regroup constants (rec role)
    const int uz1  = (20 + ii < 32) ? (20 + ii) : 31;
    const int uz2  = (ii - 12 > 0) ? (ii - 12) : 0;
    const int un   = 8 + ii;
    const int selz = (ii < 12) ? 1 : 0;

    // ---- weights (prescaled) ----
    RecW W;
    W.bA = W.bB = 0;
    W.bias0 = W.bias1 = W.bias2 = 0;
    W.c0r = W.c0z = W.c0n = W.bx0 = W.bx1 = W.bx2 = 0;
#pragma unroll
    for (int k = 0; k < GH; k++) { W.w0[k] = 0; W.w1[k] = 0; W.w2[k] = 0; }

    if (isRec) {
        const float* Wh = p.Whh[l];
        const int rowA = lane;                               // rows 0-31: r/z -> C1
        const int rowB = (32 + lane < 60) ? (32 + lane) : 59;
        const float sB = (rowB < 2 * GH) ? C1 : C2;          // z rows C1, n rows C2
#pragma unroll
        for (int k = 0; k < GH; k++) {
            W.w0[k] = pks(C1 * Wh[rowA * GH + k]);
            W.w1[k] = pks(sB * Wh[rowB * GH + k]);
        }
        W.bA = pks(C1 * p.bhh[l][rowA]);
        W.bB = pks(sB * p.bhh[l][rowB]);
        if (l == 0) {
            const float* Wi = p.Wih[0];
            W.c0r = pks(C1 * Wi[ii]);
            W.c0z = pks(C1 * Wi[GH + ii]);
            W.c0n = pks(C2 * Wi[2 * GH + ii]);
            W.bx0 = pks(C1 * p.bih[0][ii]);
            W.bx1 = pks(C1 * p.bih[0][GH + ii]);
            W.bx2 = pks(C2 * p.bih[0][2 * GH + ii]);
        }
    } else if (act) {
        const float* Wi = p.Wih[l];
#pragma unroll
        for (int k = 0; k < GH; k++) {
            W.w0[k] = pks(C1 * Wi[(i) * GH + k]);
            W.w1[k] = pks(C1 * Wi[(GH + i) * GH + k]);
            W.w2[k] = pks(C2 * Wi[(2 * GH + i) * GH + k]);
        }
        W.bias0 = pks(C1 * p.bih[l][i]);
        W.bias1 = pks(C1 * p.bih[l][GH + i]);
        W.bias2 = pks(C2 * p.bih[l][2 * GH + i]);
    }

    float* outrow0 = p.out_h + (size_t)b0 * GT * GH;
    float* outrow1 = p.out_h + (size_t)b1 * GT * GH;

    u64 hu = 0;

    __syncthreads();

    // ---- superstep pipeline (+1 drain step for the out-copy stage) ----
    for (int S = 0; S < NSUP + 1; S++) {
        const int par = S & 1;

        if (isRec) {
            const int c = S - 2 * l;
            if ((unsigned)c < (unsigned)NCHUNK) {
                u64* hb       = hch + (size_t)(l * 2 + par) * GC * GH;
                const u64* xp = xpb + (size_t)((l - 1) * 2 + (par ^ 1)) * GC * GH * XPS;
                const int tbase = c * GC;

                if (l == 0)
                    hu = rec_chunk<true>(W, hu, hb, xp, xs, tbase, ii, pa,
                                         uz1, uz2, un, selz);
                else
                    hu = rec_chunk<false>(W, hu, hb, xp, xs, tbase, ii, pa,
                                          uz1, uz2, un, selz);

                if (act && c == NCHUNK - 1) hlast[l * GH + ii] = hu;
            }
        } else {
            const int c = S - (2 * l - 1);
            if ((unsigned)c < (unsigned)NCHUNK) {
                const u64* hsrc = hch + (size_t)((l - 1) * 2 + (par ^ 1)) * GC * GH;
                u64* dst = xpb + (size_t)((l - 1) * 2 + par) * GC * GH * XPS;
                const u32 dst_a = smem_addr(dst) + (u32)ii * (XPS * 8u);

#pragma unroll 2
                for (int tin = 0; tin < GC; tin++) {
                    u64 hv[GH];
                    gather_hv(hsrc + tin * GH, hv);

                    u64 a0 = W.bias0, a1 = W.bias1, a2 = W.bias2;
                    u64 s0 = 0, s1 = 0, s2 = 0;
#pragma unroll
                    for (int k = 0; k < GH / 2; k++) {
                        a0 = fma2(W.w0[k], hv[k], a0);
                        a1 = fma2(W.w1[k], hv[k], a1);
                        a2 = fma2(W.w2[k], hv[k], a2);
                        s0 = fma2(W.w0[GH / 2 + k], hv[GH / 2 + k], s0);
                        s1 = fma2(W.w1[GH / 2 + k], hv[GH / 2 + k], s1);
                        s2 = fma2(W.w2[GH / 2 + k], hv[GH / 2 + k], s2);
                    }
                    const u32 base = dst_a + (u32)(tin * GH * XPS) * 8u;
                    sts128_pred(base, add2(a0, s0), add2(a1, s1), pa);
                    sts64_pred(base + 16u, add2(a2, s2), pa);
                }
            }

            // out-copy stage (wid 7, SMSP3): stream layer-4's finished chunk to GMEM
            if (wid == 7) {
                const int cc = S - (2 * (GL - 1) + 1);   // chunk written at S-1
                if ((unsigned)cc < (unsigned)NCHUNK) {
                    const u64* src = hch + (size_t)((GL - 1) * 2 + (par ^ 1)) * GC * GH;
                    const int tb = cc * GC;
#pragma unroll
                    for (int q = 0; q < (GC * GH) / 32; q++) {   // 10 iters
                        const int idx = q * 32 + lane;
                        const int tin = idx / GH;
                        const int iu  = idx - tin * GH;
                        float lo, hi;
                        unpack2(src[tin * GH + iu], lo, hi);
                        const size_t off = (size_t)(tb + tin) * GH + iu;
                        outrow0[off] = lo;
                        outrow1[off] = hi;
                    }
                }
            }
        }
        __syncthreads();
    }

    // ---- epilogue ----
    if (tid < GL * GH) {
        float a, b;
        unpack2(hlast[tid], a, b);
        p.out_hn[(size_t)b0 * GL * GH + tid] = a;
        p.out_hn[(size_t)b1 * GL * GH + tid] = b;
    }
    if (wid == 0) {
        float aL = 0.f, aH = 0.f;
        for (int j = lane; j < GL * GH; j += 32) {
            const float w = p.Wout[j];
            float xlo, xhi;
            unpack2(hlast[j], xlo, xhi);
            aL = fmaf(w, xlo, aL);
            aH = fmaf(w, xhi, aH);
        }
#pragma unroll
        for (int off = 16; off; off >>= 1) {
            aL += __shfl_xor_sync(0xffffffffu, aL, off);
            aH += __shfl_xor_sync(0xffffffffu, aH, off);
        }
        if (lane == 0) {
            p.out_y[b0] = aL + p.bout[0];
            p.out_y[b1] = aH + p.bout[0];
        }
    }
}

extern "C" void kernel_launch(void* const* d_in, const int* in_sizes, int n_in,
                              void* d_out, int out_size) {
    (void)in_sizes; (void)n_in; (void)out_size;

    GruParams p;
    p.x = (const float*)d_in[0];
    for (int l = 0; l < GL; l++) {
        p.Wih[l] = (const float*)d_in[1 + 4 * l + 0];
        p.Whh[l] = (const float*)d_in[1 + 4 * l + 1];
        p.bih[l] = (const float*)d_in[1 + 4 * l + 2];
        p.bhh[l] = (const float*)d_in[1 + 4 * l + 3];
    }
    p.Wout = (const float*)d_in[21];
    p.bout = (const float*)d_in[22];

    float* out = (float*)d_out;
    p.out_h  = out;
    p.out_hn = out + (size_t)GB * GT * GH;
    p.out_y  = out + (size_t)GB * GT * GH + (size_t)GB * GL * GH;

    cudaFuncSetAttribute(gru_chunked_kernel,
                         cudaFuncAttributeMaxDynamicSharedMemorySize, SMEM_SZ);
    gru_chunked_kernel<<<GB / 2, NTHREADS, SMEM_SZ>>>(p);
}

// round 12
// speedup vs baseline: 1.1824x; 1.1824x over previous
#include <cuda_runtime.h>
#include <cuda_bf16.h>
#include <cstdint>

#define GH 20        // hidden size
#define GL 5         // layers
#define GT 4096      // timesteps
#define GB 256       // batch
#define GC 16        // chunk (timesteps per superstep)
#define NCHUNK (GT / GC)                 // 256
#define NSUP   (NCHUNK + 2 * (GL - 1))   // 264 (+1 drain superstep in loop)
#define NTHREADS 256                     // 8 warps: 5 rec + 3 inp

using u32 = unsigned int;

// xp stride: 4 floats per unit -> (r,z,n,pad), one float4
#define XPS 4

// dynamic smem layout (bytes) — scalar floats now
#define XS_OFF    0
#define HCH_OFF   (GT * 4)                                   // 16384
#define XPB_OFF   (HCH_OFF + GL * 2 * GC * GH * 4)           // +12800 = 29184
#define HLAST_OFF (XPB_OFF + (GL - 1) * 2 * GC * GH * XPS * 4) // +40960 = 70144
#define SMEM_SZ   (HLAST_OFF + GL * GH * 4 + 16)             // ~70560

#define C1 (-1.4426950408889634f)   // -log2(e)
#define C2 (-2.8853900817779268f)   // -2*log2(e)

struct GruParams {
    const float* x;
    const float* Wih[GL];
    const float* Whh[GL];
    const float* bih[GL];
    const float* bhh[GL];
    const float* Wout;
    const float* bout;
    float* out_h;
    float* out_hn;
    float* out_y;
};

// ---------- predication / smem helpers ----------
__device__ __forceinline__ void sts32_pred(u32 addr, float v, int pred) {
    asm volatile("{ .reg .pred p; setp.ne.s32 p, %2, 0; @p st.shared.f32 [%0], %1; }"
                 :: "r"(addr), "f"(v), "r"(pred) : "memory");
}
__device__ __forceinline__ void sts128_pred(u32 addr, float v0, float v1, float v2, float v3, int pred) {
    asm volatile("{ .reg .pred p; setp.ne.s32 p, %4, 0; @p st.shared.v4.f32 [%0], {%1,%2,%3,%4}; }"
                 :: "r"(addr), "f"(v0), "f"(v1), "f"(v2), "r"(pred) : "memory");
}
// NOTE: v4 with 4 distinct values:
__device__ __forceinline__ void sts128_pred4(u32 addr, float v0, float v1, float v2, float v3, int pred) {
    asm volatile("{ .reg .pred p; setp.ne.s32 p, %5, 0; @p st.shared.v4.f32 [%0], {%1,%2,%3,%4}; }"
                 :: "r"(addr), "f"(v0), "f"(v1), "f"(v2), "f"(v3), "r"(pred) : "memory");
}
__device__ __forceinline__ float selpf(float a, float b, int c) {
    float r;
    asm("{ .reg .pred p; setp.ne.s32 p, %3, 0; selp.f32 %0, %1, %2, p; }"
        : "=f"(r) : "f"(a), "f"(b), "r"(c));
    return r;
}
__device__ __forceinline__ u32 smem_addr(const void* p) {
    return (u32)__cvta_generic_to_shared(p);
}

// ---------- fast activations (args pre-scaled by C1/C2) ----------
__device__ __forceinline__ float fast_exp2(float x) {
    float r; asm("ex2.approx.f32 %0, %1;" : "=f"(r) : "f"(x)); return r;
}
__device__ __forceinline__ float fast_rcp(float x) {
    float r; asm("rcp.approx.f32 %0, %1;" : "=f"(r) : "f"(x)); return r;
}

struct RecW {
    float w0[GH], w1[GH], w2[GH];
    float bA, bB;                        // rec pass biases (prescaled)
    float bias0, bias1, bias2;           // inp biases (prescaled)
    float c0r, c0z, c0n, bx0, bx1, bx2;  // layer-0 input path (prescaled)
};

__device__ __forceinline__ void gather_hv(const float* row, float* hv) {
    const float4* hp = (const float4*)row;
#pragma unroll
    for (int q = 0; q < GH / 4; q++) {
        float4 v = hp[q];
        hv[4 * q] = v.x; hv[4 * q + 1] = v.y; hv[4 * q + 2] = v.z; hv[4 * q + 3] = v.w;
    }
}

// One GRU step from gathered hv. Args arrive prescaled; h itself unscaled.
template <bool L0>
__device__ __forceinline__ float rec_body(const RecW& W, const float* hv, float hu,
                                          const float* xpt, const float* xs_t,
                                          int ii, int uz1, int uz2, int un, int selz) {
    // x inputs (prescaled)
    float xr, xz, xn;
    if (L0) {
        const float xt = *xs_t;
        xr = fmaf(W.c0r, xt, W.bx0);
        xz = fmaf(W.c0z, xt, W.bx1);
        xn = fmaf(W.c0n, xt, W.bx2);
    } else {
        float4 v = *(const float4*)(xpt + (size_t)ii * XPS);
        xr = v.x; xz = v.y; xn = v.z;
    }

    // pass A (rows 0-31) + pass B (rows 32-59), 2 accumulators each
    float aA = W.bA, aB = W.bB, sA = 0.f, sB = 0.f;
#pragma unroll
    for (int k = 0; k < GH / 2; k++) {
        aA = fmaf(W.w0[2 * k],     hv[2 * k],     aA);
        sA = fmaf(W.w0[2 * k + 1], hv[2 * k + 1], sA);
        aB = fmaf(W.w1[2 * k],     hv[2 * k],     aB);
        sB = fmaf(W.w1[2 * k + 1], hv[2 * k + 1], sB);
    }
    aA += sA;
    aB += sB;

    // regroup to unit-per-lane (rows: u=lane for r; 20+u for z; 40+u for n)
    const float azA = __shfl_sync(0xffffffffu, aA, uz1);
    const float azB = __shfl_sync(0xffffffffu, aB, uz2);
    const float an  = __shfl_sync(0xffffffffu, aB, un);
    const float az  = selpf(azA, azB, selz);

    const float sr = xr + aA;    // prescaled by C1
    const float sz = xz + az;    // prescaled by C1

    // sigmoids via ex2+rcp (prescaled args); tanh arm prescaled by C2
    const float ea  = fast_exp2(sr);
    const float r   = fast_rcp(1.0f + ea);
    const float eb  = fast_exp2(sz);
    const float z   = fast_rcp(1.0f + eb);
    const float zh  = z * hu;
    const float omz = 1.0f - z;
    const float t   = fast_exp2(fmaf(r, an, xn));
    const float n   = fmaf(2.0f, fast_rcp(1.0f + t), -1.0f);
    return fmaf(n, omz, zh);
}

// One 16-step chunk for a rec warp.
template <bool L0>
__device__ __forceinline__ float rec_chunk(const RecW& W, float hu,
                                           float* hb, const float* hb_prev,
                                           const float* xp, const float* xs, int tbase,
                                           int ii, int pa,
                                           int uz1, int uz2, int un, int selz) {
    const u32 hb_a = smem_addr(hb) + (u32)ii * 4u;
    float hv[GH];

    // tin = 0 (carry from previous chunk's opposite-parity buffer)
    __syncwarp();
    gather_hv(hb_prev + (GC - 1) * GH, hv);
    hu = rec_body<L0>(W, hv, hu, xp, xs + tbase, ii, uz1, uz2, un, selz);
    sts32_pred(hb_a, hu, pa);

#pragma unroll 3
    for (int tin = 1; tin < GC; tin++) {
        __syncwarp();
        gather_hv(hb + (tin - 1) * GH, hv);
        hu = rec_body<L0>(W, hv, hu, xp + (size_t)tin * GH * XPS, xs + tbase + tin,
                          ii, uz1, uz2, un, selz);
        sts32_pred(hb_a + (u32)(tin * GH) * 4u, hu, pa);
    }
    return hu;
}

__global__ __launch_bounds__(NTHREADS, 2) void gru_scalar_kernel(GruParams p) {
    extern __shared__ __align__(16) unsigned char sm[];
    float* xs    = (float*)(sm + XS_OFF);    // [GT] x for this batch
    float* hch   = (float*)(sm + HCH_OFF);   // [GL][2][GC][GH]
    float* xpb   = (float*)(sm + XPB_OFF);   // [GL-1][2][GC][GH][XPS]
    float* hlast = (float*)(sm + HLAST_OFF); // [GL*GH]

    const int tid  = threadIdx.x;
    const int wid  = tid >> 5;
    const int lane = tid & 31;
    const int b    = blockIdx.x;

    const float* xsrc = p.x + (size_t)b * GT;
    for (int t = tid; t < GT; t += NTHREADS) xs[t] = xsrc[t];
    for (int q = tid; q < GL * 2 * GC * GH; q += NTHREADS) hch[q] = 0.0f;

    // ---- roles ----
    const bool isRec = (wid < GL);
    int l, i;
    bool act;
    if (isRec) { l = wid; i = lane; act = (lane < GH); }
    else {
        int idx = (wid - GL) * 32 + lane;          // 0..95
        act = (idx < (GL - 1) * GH);               // 80 tasks
        l = act ? 1 + idx / GH : 1;
        i = act ? idx % GH : 0;
    }
    const int ii = (i < GH) ? i : 0;
    const int pa = act ? 1 : 0;

    // shuffle regroup constants (rec role)
    const int uz1  = (20 + ii < 32) ? (20 + ii) : 31;
    const int uz2  = (ii - 12 > 0) ? (ii - 12) : 0;
    const int un   = 8 + ii;
    const int selz = (ii < 12) ? 1 : 0;

    // ---- weights (prescaled) ----
    RecW W;
    W.bA = W.bB = 0.f;
    W.bias0 = W.bias1 = W.bias2 = 0.f;
    W.c0r = W.c0z = W.c0n = W.bx0 = W.bx1 = W.bx2 = 0.f;
#pragma unroll
    for (int k = 0; k < GH; k++) { W.w0[k] = 0.f; W.w1[k] = 0.f; W.w2[k] = 0.f; }

    if (isRec) {
        const float* Wh = p.Whh[l];
        const int rowA = lane;                               // rows 0-31: r/z -> C1
        const int rowB = (32 + lane < 60) ? (32 + lane) : 59;
        const float sB = (rowB < 2 * GH) ? C1 : C2;          // z rows C1, n rows C2
#pragma unroll
        for (int k = 0; k < GH; k++) {
            W.w0[k] = C1 * Wh[rowA * GH + k];
            W.w1[k] = sB * Wh[rowB * GH + k];
        }
        W.bA = C1 * p.bhh[l][rowA];
        W.bB = sB * p.bhh[l][rowB];
        if (l == 0) {
            const float* Wi = p.Wih[0];
            W.c0r = C1 * Wi[ii];
            W.c0z = C1 * Wi[GH + ii];
            W.c0n = C2 * Wi[2 * GH + ii];
            W.bx0 = C1 * p.bih[0][ii];
            W.bx1 = C1 * p.bih[0][GH + ii];
            W.bx2 = C2 * p.bih[0][2 * GH + ii];
        }
    } else if (act) {
        const float* Wi = p.Wih[l];
#pragma unroll
        for (int k = 0; k < GH; k++) {
            W.w0[k] = C1 * Wi[(i) * GH + k];
            W.w1[k] = C1 * Wi[(GH + i) * GH + k];
            W.w2[k] = C2 * Wi[(2 * GH + i) * GH + k];
        }
        W.bias0 = C1 * p.bih[l][i];
        W.bias1 = C1 * p.bih[l][GH + i];
        W.bias2 = C2 * p.bih[l][2 * GH + i];
    }

    float* outrow = p.out_h + (size_t)b * GT * GH;

    float hu = 0.f;

    __syncthreads();

    // ---- superstep pipeline (+1 drain step for the out-copy stage) ----
    for (int S = 0; S < NSUP + 1; S++) {
        const int par = S & 1;

        if (isRec) {
            const int c = S - 2 * l;
            if ((unsigned)c < (unsigned)NCHUNK) {
                float* hb            = hch + (size_t)(l * 2 + par) * GC * GH;
                const float* hb_prev = hch + (size_t)(l * 2 + (par ^ 1)) * GC * GH;
                const float* xp      = xpb + (size_t)((l - 1) * 2 + (par ^ 1)) * GC * GH * XPS;
                const int tbase = c * GC;

                if (l == 0)
                    hu = rec_chunk<true>(W, hu, hb, hb_prev, xp, xs, tbase, ii, pa,
                                         uz1, uz2, un, selz);
                else
                    hu = rec_chunk<false>(W, hu, hb, hb_prev, xp, xs, tbase, ii, pa,
                                          uz1, uz2, un, selz);

                if (act && c == NCHUNK - 1) hlast[l * GH + ii] = hu;
            }
        } else {
            const int c = S - (2 * l - 1);
            if ((unsigned)c < (unsigned)NCHUNK) {
                const float* hsrc = hch + (size_t)((l - 1) * 2 + (par ^ 1)) * GC * GH;
                float* dst = xpb + (size_t)((l - 1) * 2 + par) * GC * GH * XPS;
                const u32 dst_a = smem_addr(dst) + (u32)ii * (XPS * 4u);

#pragma unroll 2
                for (int tin = 0; tin < GC; tin++) {
                    float hv[GH];
                    gather_hv(hsrc + tin * GH, hv);

                    float a0 = W.bias0, a1 = W.bias1, a2 = W.bias2;
                    float s0 = 0.f, s1 = 0.f, s2 = 0.f;
#pragma unroll
                    for (int k = 0; k < GH / 2; k++) {
                        a0 = fmaf(W.w0[k], hv[k], a0);
                        a1 = fmaf(W.w1[k], hv[k], a1);
                        a2 = fmaf(W.w2[k], hv[k], a2);
                        s0 = fmaf(W.w0[GH / 2 + k], hv[GH / 2 + k], s0);
                        s1 = fmaf(W.w1[GH / 2 + k], hv[GH / 2 + k], s1);
                        s2 = fmaf(W.w2[GH / 2 + k], hv[GH / 2 + k], s2);
                    }
                    const u32 base = dst_a + (u32)(tin * GH * XPS) * 4u;
                    sts128_pred4(base, a0 + s0, a1 + s1, a2 + s2, 0.0f, pa);
                }
            }

            // out-copy stage (wid 7): stream layer-4's finished chunk to GMEM
            if (wid == 7) {
                const int cc = S - (2 * (GL - 1) + 1);   // chunk written at S-1
                if ((unsigned)cc < (unsigned)NCHUNK) {
                    const float* src = hch + (size_t)((GL - 1) * 2 + (par ^ 1)) * GC * GH;
                    float* dstg = outrow + (size_t)cc * GC * GH;   // 320 contiguous floats
#pragma unroll
                    for (int q = 0; q < (GC * GH) / 32; q++) {     // 10 iters, coalesced
                        const int idx = q * 32 + lane;
                        dstg[idx] = src[idx];
                    }
                }
            }
        }
        __syncthreads();
    }

    // ---- epilogue ----
    if (tid < GL * GH)
        p.out_hn[(size_t)b * GL * GH + tid] = hlast[tid];

    if (wid == 0) {
        float acc = 0.f;
        for (int j = lane; j < GL * GH; j += 32)
            acc = fmaf(p.Wout[j], hlast[j], acc);
#pragma unroll
        for (int off = 16; off; off >>= 1)
            acc += __shfl_xor_sync(0xffffffffu, acc, off);
        if (lane == 0)
            p.out_y[b] = acc + p.bout[0];
    }
}

extern "C" void kernel_launch(void* const* d_in, const int* in_sizes, int n_in,
                              void* d_out, int out_size) {
    (void)in_sizes; (void)n_in; (void)out_size;

    GruParams p;
    p.x = (const float*)d_in[0];
    for (int l = 0; l < GL; l++) {
        p.Wih[l] = (const float*)d_in[1 + 4 * l + 0];
        p.Whh[l] = (const float*)d_in[1 + 4 * l + 1];
        p.bih[l] = (const float*)d_in[1 + 4 * l + 2];
        p.bhh[l] = (const float*)d_in[1 + 4 * l + 3];
    }
    p.Wout = (const float*)d_in[21];
    p.bout = (const float*)d_in[22];

    float* out = (float*)d_out;
    p.out_h  = out;
    p.out_hn = out + (size_t)GB * GT * GH;
    p.out_y  = out + (size_t)GB * GT * GH + (size_t)GB * GL * GH;

    cudaFuncSetAttribute(gru_scalar_kernel,
                         cudaFuncAttributeMaxDynamicSharedMemorySize, SMEM_SZ);
    gru_scalar_kernel<<<GB, NTHREADS, SMEM_SZ>>>(p);
}